// round 2
// baseline (speedup 1.0000x reference)
#include <cuda_runtime.h>
#include <cuda_bf16.h>

#define N_NODES 50000
#define N_EDGES 800000
#define IN_F 256
#define HFD 128   // HEADS * OUT_FEATS
#define NHEAD 4

// -------- scratch (device globals; no allocation allowed) --------
__device__ float g_feat_hf[N_NODES * HFD];   // projected features [N,128]
__device__ float g_el[N_NODES * NHEAD];      // attn_l dot  [N,4]
__device__ float g_er[N_NODES * NHEAD];      // attn_r dot  [N,4]
__device__ float g_s[N_NODES * HFD];         // softmax denominator
__device__ float g_num[N_NODES * HFD];       // softmax-weighted numerator

// =================================================================
// Kernel 1: feat_hf = feat @ W_fc^T   (M=50000, K=256, N=128)
// Register-tiled fp32 GEMM: block tile 64x128, thread tile 8x4.
// =================================================================
__global__ __launch_bounds__(256) void k_gemm(const float* __restrict__ feat,
                                              const float* __restrict__ Wfc) {
    __shared__ float As[16][68];    // [k][m], padded
    __shared__ float Bs[16][132];   // [k][n], padded

    const int tid = threadIdx.x;
    const int row0 = blockIdx.x * 64;
    const int tx = tid & 31;        // n-dir: col = tx*4
    const int ty = tid >> 5;        // m-dir: row = ty*8

    float acc[8][4];
#pragma unroll
    for (int i = 0; i < 8; i++)
#pragma unroll
        for (int j = 0; j < 4; j++) acc[i][j] = 0.f;

    // A-load mapping: 64 rows x 16 k per chunk; 1 float4 per thread
    const int a_m = tid >> 2;            // 0..63
    const int a_k = (tid & 3) * 4;       // 0,4,8,12
    int a_row = row0 + a_m;
    if (a_row >= N_NODES) a_row = N_NODES - 1;   // clamp (stores guarded)
    const float* a_ptr = feat + (size_t)a_row * IN_F + a_k;

    for (int k0 = 0; k0 < IN_F; k0 += 16) {
        // load A chunk
        float4 av = *(const float4*)(a_ptr + k0);
        As[a_k + 0][a_m] = av.x;
        As[a_k + 1][a_m] = av.y;
        As[a_k + 2][a_m] = av.z;
        As[a_k + 3][a_m] = av.w;
        // load B chunk: Bs[k][n] = Wfc[n*256 + k0 + k]; 2 float4 per thread
#pragma unroll
        for (int i = 0; i < 2; i++) {
            int lin = tid + i * 256;     // 0..511
            int bn = lin >> 2;           // 0..127
            int bk = (lin & 3) * 4;
            float4 bv = *(const float4*)(Wfc + (size_t)bn * IN_F + k0 + bk);
            Bs[bk + 0][bn] = bv.x;
            Bs[bk + 1][bn] = bv.y;
            Bs[bk + 2][bn] = bv.z;
            Bs[bk + 3][bn] = bv.w;
        }
        __syncthreads();

#pragma unroll
        for (int k = 0; k < 16; k++) {
            float4 b = *(const float4*)&Bs[k][tx * 4];
            float4 a0 = *(const float4*)&As[k][ty * 8];
            float4 a1 = *(const float4*)&As[k][ty * 8 + 4];
            float am[8] = {a0.x, a0.y, a0.z, a0.w, a1.x, a1.y, a1.z, a1.w};
            float bn4[4] = {b.x, b.y, b.z, b.w};
#pragma unroll
            for (int i = 0; i < 8; i++)
#pragma unroll
                for (int j = 0; j < 4; j++) acc[i][j] = fmaf(am[i], bn4[j], acc[i][j]);
        }
        __syncthreads();
    }

#pragma unroll
    for (int i = 0; i < 8; i++) {
        int r = row0 + ty * 8 + i;
        if (r < N_NODES) {
            float4 o = make_float4(acc[i][0], acc[i][1], acc[i][2], acc[i][3]);
            *(float4*)&g_feat_hf[(size_t)r * HFD + tx * 4] = o;
        }
    }
}

// =================================================================
// Kernel 2: el[n,h] = sum_f feat_hf[n,h,f]*attn_l[h,f]; same for er.
// One warp per node.
// =================================================================
__global__ __launch_bounds__(256) void k_elr(const float* __restrict__ attn_l,
                                             const float* __restrict__ attn_r) {
    int wid = (blockIdx.x * blockDim.x + threadIdx.x) >> 5;
    if (wid >= N_NODES) return;
    int lane = threadIdx.x & 31;

    float4 v = *(const float4*)&g_feat_hf[(size_t)wid * HFD + lane * 4];
    float4 al = *(const float4*)&attn_l[lane * 4];
    float4 ar = *(const float4*)&attn_r[lane * 4];
    float pl = v.x * al.x + v.y * al.y + v.z * al.z + v.w * al.w;
    float pr = v.x * ar.x + v.y * ar.y + v.z * ar.z + v.w * ar.w;
    // reduce within each 8-lane head group (lanes 8h..8h+7)
#pragma unroll
    for (int o = 1; o < 8; o <<= 1) {
        pl += __shfl_xor_sync(0xffffffffu, pl, o);
        pr += __shfl_xor_sync(0xffffffffu, pr, o);
    }
    if ((lane & 7) == 0) {
        int h = lane >> 3;
        g_el[wid * NHEAD + h] = pl;
        g_er[wid * NHEAD + h] = pr;
    }
}

// =================================================================
// Kernel 3: zero the accumulators (graph replays need fresh zeros)
// =================================================================
__global__ __launch_bounds__(256) void k_zero() {
    const int n4 = N_NODES * HFD / 4;
    float4 z = make_float4(0.f, 0.f, 0.f, 0.f);
    for (int i = blockIdx.x * blockDim.x + threadIdx.x; i < n4;
         i += gridDim.x * blockDim.x) {
        ((float4*)g_s)[i] = z;
        ((float4*)g_num)[i] = z;
    }
}

// =================================================================
// Kernel 4: edge pass. One warp per edge, 4 contiguous (h,f) per lane.
//   logit = leaky_relu(el[s,h]+er[d,h] + w*W_edge[h,f])
//   red.v4: g_s[d] += exp(logit); g_num[d] += exp(logit)*ft[s]
// (softmax shift omitted: result is shift-invariant and logits are O(1))
// =================================================================
__global__ __launch_bounds__(256) void k_edge(const float* __restrict__ ew,
                                              const int* __restrict__ src,
                                              const int* __restrict__ dst,
                                              const float* __restrict__ Wedge) {
    int e = (blockIdx.x * blockDim.x + threadIdx.x) >> 5;
    if (e >= N_EDGES) return;
    int lane = threadIdx.x & 31;

    int s = __ldg(&src[e]);
    int d = __ldg(&dst[e]);
    float w = __ldg(&ew[e]);

    int h = lane >> 3;
    float c = g_el[s * NHEAD + h] + g_er[d * NHEAD + h];

    float4 ft = *(const float4*)&g_feat_hf[(size_t)s * HFD + lane * 4];
    float4 We = *(const float4*)&Wedge[lane * 4];

    float v0 = c + w * We.x;  v0 = fmaxf(v0, 0.2f * v0);
    float v1 = c + w * We.y;  v1 = fmaxf(v1, 0.2f * v1);
    float v2 = c + w * We.z;  v2 = fmaxf(v2, 0.2f * v2);
    float v3 = c + w * We.w;  v3 = fmaxf(v3, 0.2f * v3);

    float e0 = __expf(v0), e1 = __expf(v1), e2 = __expf(v2), e3 = __expf(v3);
    float n0 = e0 * ft.x, n1 = e1 * ft.y, n2 = e2 * ft.z, n3 = e3 * ft.w;

    float* ps = &g_s[(size_t)d * HFD + lane * 4];
    float* pn = &g_num[(size_t)d * HFD + lane * 4];
    asm volatile("red.global.add.v4.f32 [%0], {%1,%2,%3,%4};"
                 :: "l"(ps), "f"(e0), "f"(e1), "f"(e2), "f"(e3) : "memory");
    asm volatile("red.global.add.v4.f32 [%0], {%1,%2,%3,%4};"
                 :: "l"(pn), "f"(n0), "f"(n1), "f"(n2), "f"(n3) : "memory");
}

// =================================================================
// Kernel 5: out = num/s + bias   (s==0 -> isolated node -> just bias)
// =================================================================
__global__ __launch_bounds__(256) void k_final(float* __restrict__ out,
                                               const float* __restrict__ bias) {
    int i = blockIdx.x * blockDim.x + threadIdx.x;
    const int n4 = N_NODES * HFD / 4;
    if (i >= n4) return;
    int hf4 = (i * 4) & (HFD - 1);
    float4 sv = ((const float4*)g_s)[i];
    float4 nv = ((const float4*)g_num)[i];
    float4 b = *(const float4*)&bias[hf4];
    float4 o;
    o.x = (sv.x > 0.f ? nv.x / sv.x : 0.f) + b.x;
    o.y = (sv.y > 0.f ? nv.y / sv.y : 0.f) + b.y;
    o.z = (sv.z > 0.f ? nv.z / sv.z : 0.f) + b.z;
    o.w = (sv.w > 0.f ? nv.w / sv.w : 0.f) + b.w;
    ((float4*)out)[i] = o;
}

// =================================================================
extern "C" void kernel_launch(void* const* d_in, const int* in_sizes, int n_in,
                              void* d_out, int out_size) {
    const float* feat   = (const float*)d_in[0];
    const float* ew     = (const float*)d_in[1];
    const int*   src    = (const int*)d_in[2];
    const int*   dst    = (const int*)d_in[3];
    const float* Wfc    = (const float*)d_in[4];
    const float* Wedge  = (const float*)d_in[5];
    const float* attn_l = (const float*)d_in[6];
    const float* attn_r = (const float*)d_in[7];
    const float* bias   = (const float*)d_in[8];
    float* out = (float*)d_out;

    (void)in_sizes; (void)n_in; (void)out_size;

    k_gemm<<<(N_NODES + 63) / 64, 256>>>(feat, Wfc);
    k_elr<<<(N_NODES * 32 + 255) / 256, 256>>>(attn_l, attn_r);
    k_zero<<<1184, 256>>>();
    k_edge<<<(N_EDGES * 32 + 255) / 256, 256>>>(ew, src, dst, Wedge);
    k_final<<<(N_NODES * HFD / 4 + 255) / 256, 256>>>(out, bias);
}

// round 3
// speedup vs baseline: 1.3746x; 1.3746x over previous
#include <cuda_runtime.h>
#include <cuda_bf16.h>

#define N_NODES 50000
#define N_EDGES 800000
#define IN_F 256
#define HFD 128   // HEADS * OUT_FEATS
#define NHEAD 4
#define SCAN_B 196   // ceil(50000/256)

// -------- scratch (device globals; no allocation allowed) --------
__device__ float g_feat_hf[N_NODES * HFD];   // projected features [N,128]
__device__ float g_el[N_NODES * NHEAD];      // attn_l dot  [N,4]
__device__ float g_er[N_NODES * NHEAD];      // attn_r dot  [N,4]
__device__ int   g_deg[N_NODES];             // per-dst degree
__device__ int   g_rowptr[N_NODES + 1];      // CSR row pointers
__device__ int   g_cursor[N_NODES];          // scatter cursors
__device__ int   g_poff[SCAN_B];             // scan partials
__device__ int2  g_edge[N_EDGES];            // (src, bits(weight)) sorted by dst

// =================================================================
// Kernel 1: feat_hf = feat @ W_fc^T   (M=50000, K=256, N=128)
// Register-tiled fp32 GEMM: block tile 64x128, thread tile 8x4.
// Also zeroes g_deg for this block's rows (free).
// =================================================================
__global__ __launch_bounds__(256) void k_gemm(const float* __restrict__ feat,
                                              const float* __restrict__ Wfc) {
    __shared__ float As[16][68];    // [k][m], padded
    __shared__ float Bs[16][132];   // [k][n], padded

    const int tid = threadIdx.x;
    const int row0 = blockIdx.x * 64;

    if (tid < 64) {
        int r = row0 + tid;
        if (r < N_NODES) g_deg[r] = 0;
    }

    const int tx = tid & 31;        // n-dir: col = tx*4
    const int ty = tid >> 5;        // m-dir: row = ty*8

    float acc[8][4];
#pragma unroll
    for (int i = 0; i < 8; i++)
#pragma unroll
        for (int j = 0; j < 4; j++) acc[i][j] = 0.f;

    const int a_m = tid >> 2;            // 0..63
    const int a_k = (tid & 3) * 4;       // 0,4,8,12
    int a_row = row0 + a_m;
    if (a_row >= N_NODES) a_row = N_NODES - 1;   // clamp (stores guarded)
    const float* a_ptr = feat + (size_t)a_row * IN_F + a_k;

    for (int k0 = 0; k0 < IN_F; k0 += 16) {
        float4 av = *(const float4*)(a_ptr + k0);
        As[a_k + 0][a_m] = av.x;
        As[a_k + 1][a_m] = av.y;
        As[a_k + 2][a_m] = av.z;
        As[a_k + 3][a_m] = av.w;
#pragma unroll
        for (int i = 0; i < 2; i++) {
            int lin = tid + i * 256;     // 0..511
            int bn = lin >> 2;           // 0..127
            int bk = (lin & 3) * 4;
            float4 bv = *(const float4*)(Wfc + (size_t)bn * IN_F + k0 + bk);
            Bs[bk + 0][bn] = bv.x;
            Bs[bk + 1][bn] = bv.y;
            Bs[bk + 2][bn] = bv.z;
            Bs[bk + 3][bn] = bv.w;
        }
        __syncthreads();

#pragma unroll
        for (int k = 0; k < 16; k++) {
            float4 b = *(const float4*)&Bs[k][tx * 4];
            float4 a0 = *(const float4*)&As[k][ty * 8];
            float4 a1 = *(const float4*)&As[k][ty * 8 + 4];
            float am[8] = {a0.x, a0.y, a0.z, a0.w, a1.x, a1.y, a1.z, a1.w};
            float bn4[4] = {b.x, b.y, b.z, b.w};
#pragma unroll
            for (int i = 0; i < 8; i++)
#pragma unroll
                for (int j = 0; j < 4; j++) acc[i][j] = fmaf(am[i], bn4[j], acc[i][j]);
        }
        __syncthreads();
    }

#pragma unroll
    for (int i = 0; i < 8; i++) {
        int r = row0 + ty * 8 + i;
        if (r < N_NODES) {
            float4 o = make_float4(acc[i][0], acc[i][1], acc[i][2], acc[i][3]);
            *(float4*)&g_feat_hf[(size_t)r * HFD + tx * 4] = o;
        }
    }
}

// =================================================================
// Kernel 2: el[n,h], er[n,h] dots. One warp per node.
// =================================================================
__global__ __launch_bounds__(256) void k_elr(const float* __restrict__ attn_l,
                                             const float* __restrict__ attn_r) {
    int wid = (blockIdx.x * blockDim.x + threadIdx.x) >> 5;
    if (wid >= N_NODES) return;
    int lane = threadIdx.x & 31;

    float4 v = *(const float4*)&g_feat_hf[(size_t)wid * HFD + lane * 4];
    float4 al = *(const float4*)&attn_l[lane * 4];
    float4 ar = *(const float4*)&attn_r[lane * 4];
    float pl = v.x * al.x + v.y * al.y + v.z * al.z + v.w * al.w;
    float pr = v.x * ar.x + v.y * ar.y + v.z * ar.z + v.w * ar.w;
#pragma unroll
    for (int o = 1; o < 8; o <<= 1) {
        pl += __shfl_xor_sync(0xffffffffu, pl, o);
        pr += __shfl_xor_sync(0xffffffffu, pr, o);
    }
    if ((lane & 7) == 0) {
        int h = lane >> 3;
        g_el[wid * NHEAD + h] = pl;
        g_er[wid * NHEAD + h] = pr;
    }
}

// =================================================================
// Kernel 3: histogram of dst degrees
// =================================================================
__global__ __launch_bounds__(256) void k_hist(const int* __restrict__ dst) {
    int e = blockIdx.x * blockDim.x + threadIdx.x;
    if (e < N_EDGES) atomicAdd(&g_deg[dst[e]], 1);
}

// ---------- block-wide exclusive scan helper (256 threads) ----------
__device__ __forceinline__ int block_excl_scan_256(int v) {
    int lane = threadIdx.x & 31, wid = threadIdx.x >> 5;
    int incl = v;
#pragma unroll
    for (int o = 1; o < 32; o <<= 1) {
        int n = __shfl_up_sync(0xffffffffu, incl, o);
        if (lane >= o) incl += n;
    }
    __shared__ int wsum[8];
    if (lane == 31) wsum[wid] = incl;
    __syncthreads();
    int woff = 0;
    if (wid == 0 && lane < 8) {
        int wv = wsum[lane];
        int acc = wv;
#pragma unroll
        for (int o = 1; o < 8; o <<= 1) {
            int n = __shfl_up_sync(0xffu, acc, o);
            if (lane >= o) acc += n;
        }
        wsum[lane] = acc - wv;   // exclusive warp offsets
    }
    __syncthreads();
    woff = wsum[wid];
    return incl - v + woff;
}

// =================================================================
// Kernel 4a: per-block partial sums of deg
// =================================================================
__global__ __launch_bounds__(256) void k_scanA() {
    int idx = blockIdx.x * 256 + threadIdx.x;
    int v = (idx < N_NODES) ? g_deg[idx] : 0;
    // block reduce via scan (reuse helper: last thread's excl+v = total)
    int excl = block_excl_scan_256(v);
    if (threadIdx.x == 255) g_poff[blockIdx.x] = excl + v;
}

// =================================================================
// Kernel 4b: exclusive scan of the 196 partials (1 block)
// =================================================================
__global__ __launch_bounds__(256) void k_scanB() {
    int t = threadIdx.x;
    int v = (t < SCAN_B) ? g_poff[t] : 0;
    int excl = block_excl_scan_256(v);
    if (t < SCAN_B) g_poff[t] = excl;
}

// =================================================================
// Kernel 4c: final rowptr/cursor
// =================================================================
__global__ __launch_bounds__(256) void k_scanC() {
    int idx = blockIdx.x * 256 + threadIdx.x;
    int v = (idx < N_NODES) ? g_deg[idx] : 0;
    int excl = block_excl_scan_256(v) + g_poff[blockIdx.x];
    if (idx < N_NODES) {
        g_rowptr[idx] = excl;
        g_cursor[idx] = excl;
        if (idx == N_NODES - 1) g_rowptr[N_NODES] = excl + v;
    }
}

// =================================================================
// Kernel 5: scatter edges into CSR order (by dst)
// =================================================================
__global__ __launch_bounds__(256) void k_scatter(const int* __restrict__ src,
                                                 const int* __restrict__ dst,
                                                 const float* __restrict__ ew) {
    int e = blockIdx.x * blockDim.x + threadIdx.x;
    if (e >= N_EDGES) return;
    int d = dst[e];
    int pos = atomicAdd(&g_cursor[d], 1);
    g_edge[pos] = make_int2(src[e], __float_as_int(ew[e]));
}

// =================================================================
// Kernel 6: aggregation. One warp per dst node; accumulate in regs.
//   out[d,hf] = (sum_e exp(lrelu(el[s]+er[d]+w*We)) * ft[s]) / den + bias
// =================================================================
__global__ __launch_bounds__(256) void k_agg(float* __restrict__ out,
                                             const float* __restrict__ Wedge,
                                             const float* __restrict__ bias) {
    int d = (blockIdx.x * blockDim.x + threadIdx.x) >> 5;
    if (d >= N_NODES) return;
    int lane = threadIdx.x & 31;
    int h = lane >> 3;

    float4 We = *(const float4*)&Wedge[lane * 4];
    float4 b4 = *(const float4*)&bias[lane * 4];

    int beg = g_rowptr[d];
    int end = g_rowptr[d + 1];
    float er_h = g_er[d * NHEAD + h];

    float4 num = make_float4(0.f, 0.f, 0.f, 0.f);
    float4 den = make_float4(0.f, 0.f, 0.f, 0.f);

    for (int base = beg; base < end; base += 32) {
        int m = end - base;
        if (m > 32) m = 32;
        int2 sw = make_int2(0, 0);
        if (lane < m) sw = g_edge[base + lane];
        for (int j = 0; j < m; j++) {
            int   s = __shfl_sync(0xffffffffu, sw.x, j);
            float w = __int_as_float(__shfl_sync(0xffffffffu, sw.y, j));
            float c = __ldg(&g_el[s * NHEAD + h]) + er_h;
            float4 ft = *(const float4*)&g_feat_hf[(size_t)s * HFD + lane * 4];

            float v0 = c + w * We.x;  v0 = fmaxf(v0, 0.2f * v0);
            float v1 = c + w * We.y;  v1 = fmaxf(v1, 0.2f * v1);
            float v2 = c + w * We.z;  v2 = fmaxf(v2, 0.2f * v2);
            float v3 = c + w * We.w;  v3 = fmaxf(v3, 0.2f * v3);

            float e0 = __expf(v0), e1 = __expf(v1), e2 = __expf(v2), e3 = __expf(v3);
            den.x += e0; den.y += e1; den.z += e2; den.w += e3;
            num.x = fmaf(e0, ft.x, num.x);
            num.y = fmaf(e1, ft.y, num.y);
            num.z = fmaf(e2, ft.z, num.z);
            num.w = fmaf(e3, ft.w, num.w);
        }
    }

    float4 o;
    if (end > beg) {
        o.x = num.x / den.x + b4.x;
        o.y = num.y / den.y + b4.y;
        o.z = num.z / den.z + b4.z;
        o.w = num.w / den.w + b4.w;
    } else {
        o = b4;   // isolated node: just bias
    }
    *(float4*)&out[(size_t)d * HFD + lane * 4] = o;
}

// =================================================================
extern "C" void kernel_launch(void* const* d_in, const int* in_sizes, int n_in,
                              void* d_out, int out_size) {
    const float* feat   = (const float*)d_in[0];
    const float* ew     = (const float*)d_in[1];
    const int*   src    = (const int*)d_in[2];
    const int*   dst    = (const int*)d_in[3];
    const float* Wfc    = (const float*)d_in[4];
    const float* Wedge  = (const float*)d_in[5];
    const float* attn_l = (const float*)d_in[6];
    const float* attn_r = (const float*)d_in[7];
    const float* bias   = (const float*)d_in[8];
    float* out = (float*)d_out;

    (void)in_sizes; (void)n_in; (void)out_size;

    k_gemm<<<(N_NODES + 63) / 64, 256>>>(feat, Wfc);              // + deg zero
    k_elr<<<(N_NODES * 32 + 255) / 256, 256>>>(attn_l, attn_r);
    k_hist<<<(N_EDGES + 255) / 256, 256>>>(dst);
    k_scanA<<<SCAN_B, 256>>>();
    k_scanB<<<1, 256>>>();
    k_scanC<<<SCAN_B, 256>>>();
    k_scatter<<<(N_EDGES + 255) / 256, 256>>>(src, dst, ew);
    k_agg<<<(N_NODES * 32 + 255) / 256, 256>>>(out, Wedge, bias);
}

// round 4
// speedup vs baseline: 1.6191x; 1.1778x over previous
#include <cuda_runtime.h>
#include <cuda_bf16.h>

#define N_NODES 50000
#define N_EDGES 800000
#define IN_F 256
#define HFD 128   // HEADS * OUT_FEATS
#define NHEAD 4
#define SCAN_B 196   // ceil(50000/256)

// -------- scratch (device globals; no allocation allowed) --------
__device__ float g_feat_hf[N_NODES * HFD];   // projected features [N,128]
__device__ float g_el[N_NODES * NHEAD];      // attn_l dot  [N,4]
__device__ float g_er[N_NODES * NHEAD];      // attn_r dot  [N,4]
__device__ int   g_deg[N_NODES];             // per-dst degree
__device__ int   g_rowptr[N_NODES + 1];      // CSR row pointers
__device__ int   g_cursor[N_NODES];          // scatter cursors
__device__ int   g_poff[SCAN_B];             // scan partials
__device__ int2  g_edge[N_EDGES];            // (src, bits(weight)) sorted by dst

__device__ __forceinline__ unsigned f2tf32(float f) {
    unsigned u;
    asm("cvt.rna.tf32.f32 %0, %1;" : "=r"(u) : "f"(f));
    return u;
}

// =================================================================
// Kernel 1: feat_hf = feat @ W_fc^T   (M=50000, K=256, N=128)
// tf32 mma.sync, block tile 128x128, 8 warps (2x4), warp tile 64x32.
// Also zeroes g_deg for this block's rows (free).
// =================================================================
__global__ __launch_bounds__(256) void k_gemm(const float* __restrict__ feat,
                                              const float* __restrict__ Wfc) {
    __shared__ unsigned As[32][132];   // [k][m], tf32 bits, padded
    __shared__ unsigned Bs[32][132];   // [k][n], tf32 bits, padded

    const int tid = threadIdx.x;
    const int lane = tid & 31;
    const int wid = tid >> 5;
    const int warp_m = wid >> 2;       // 0..1
    const int warp_n = wid & 3;        // 0..3
    const int row0 = blockIdx.x * 128;

    if (tid < 128) {
        int r = row0 + tid;
        if (r < N_NODES) g_deg[r] = 0;
    }

    float acc[4][4][4];                // [mtile][ntile][frag]
#pragma unroll
    for (int i = 0; i < 4; i++)
#pragma unroll
        for (int j = 0; j < 4; j++)
#pragma unroll
            for (int q = 0; q < 4; q++) acc[i][j][q] = 0.f;

    const int gq = lane >> 2;          // group id 0..7
    const int tg = lane & 3;           // thread-in-group 0..3

    for (int chunk = 0; chunk < 8; chunk++) {
        const int kglob = chunk * 32;
        // A chunk: 128 rows x 32 k; 1024 float4, 4 per thread. transpose to [k][m]
#pragma unroll
        for (int i = 0; i < 4; i++) {
            int idx = tid + i * 256;
            int m = idx & 127;
            int k4 = (idx >> 7) * 4;
            int row = row0 + m;
            if (row >= N_NODES) row = N_NODES - 1;
            float4 v = *(const float4*)(feat + (size_t)row * IN_F + kglob + k4);
            As[k4 + 0][m] = f2tf32(v.x);
            As[k4 + 1][m] = f2tf32(v.y);
            As[k4 + 2][m] = f2tf32(v.z);
            As[k4 + 3][m] = f2tf32(v.w);
        }
        // B chunk: Bs[k][n] = Wfc[n][kglob+k]
#pragma unroll
        for (int i = 0; i < 4; i++) {
            int idx = tid + i * 256;
            int n = idx & 127;
            int k4 = (idx >> 7) * 4;
            float4 v = *(const float4*)(Wfc + (size_t)n * IN_F + kglob + k4);
            Bs[k4 + 0][n] = f2tf32(v.x);
            Bs[k4 + 1][n] = f2tf32(v.y);
            Bs[k4 + 2][n] = f2tf32(v.z);
            Bs[k4 + 3][n] = f2tf32(v.w);
        }
        __syncthreads();

#pragma unroll
        for (int kk = 0; kk < 4; kk++) {
            const int kb = kk * 8;
            unsigned a[4][4], b[4][2];
#pragma unroll
            for (int mt = 0; mt < 4; mt++) {
                int rs = warp_m * 64 + mt * 16;
                a[mt][0] = As[kb + tg][rs + gq];
                a[mt][1] = As[kb + tg][rs + gq + 8];
                a[mt][2] = As[kb + tg + 4][rs + gq];
                a[mt][3] = As[kb + tg + 4][rs + gq + 8];
            }
#pragma unroll
            for (int nt = 0; nt < 4; nt++) {
                int ns = warp_n * 32 + nt * 8;
                b[nt][0] = Bs[kb + tg][ns + gq];
                b[nt][1] = Bs[kb + tg + 4][ns + gq];
            }
#pragma unroll
            for (int mt = 0; mt < 4; mt++)
#pragma unroll
                for (int nt = 0; nt < 4; nt++) {
                    asm volatile(
                        "mma.sync.aligned.m16n8k8.row.col.f32.tf32.tf32.f32 "
                        "{%0,%1,%2,%3}, {%4,%5,%6,%7}, {%8,%9}, {%0,%1,%2,%3};"
                        : "+f"(acc[mt][nt][0]), "+f"(acc[mt][nt][1]),
                          "+f"(acc[mt][nt][2]), "+f"(acc[mt][nt][3])
                        : "r"(a[mt][0]), "r"(a[mt][1]), "r"(a[mt][2]), "r"(a[mt][3]),
                          "r"(b[nt][0]), "r"(b[nt][1]));
                }
        }
        __syncthreads();
    }

    // epilogue: c0 (r=gq, col=2*tg), c1 (col+1), c2 (r=gq+8), c3
#pragma unroll
    for (int mt = 0; mt < 4; mt++) {
#pragma unroll
        for (int nt = 0; nt < 4; nt++) {
            int col = warp_n * 32 + nt * 8 + tg * 2;
            int r0 = row0 + warp_m * 64 + mt * 16 + gq;
            if (r0 < N_NODES) {
                float2 v = make_float2(acc[mt][nt][0], acc[mt][nt][1]);
                *(float2*)&g_feat_hf[(size_t)r0 * HFD + col] = v;
            }
            int r1 = r0 + 8;
            if (r1 < N_NODES) {
                float2 v = make_float2(acc[mt][nt][2], acc[mt][nt][3]);
                *(float2*)&g_feat_hf[(size_t)r1 * HFD + col] = v;
            }
        }
    }
}

// =================================================================
// Kernel 2: el[n,h], er[n,h] dots. One warp per node.
// =================================================================
__global__ __launch_bounds__(256) void k_elr(const float* __restrict__ attn_l,
                                             const float* __restrict__ attn_r) {
    int wid = (blockIdx.x * blockDim.x + threadIdx.x) >> 5;
    if (wid >= N_NODES) return;
    int lane = threadIdx.x & 31;

    float4 v = *(const float4*)&g_feat_hf[(size_t)wid * HFD + lane * 4];
    float4 al = *(const float4*)&attn_l[lane * 4];
    float4 ar = *(const float4*)&attn_r[lane * 4];
    float pl = v.x * al.x + v.y * al.y + v.z * al.z + v.w * al.w;
    float pr = v.x * ar.x + v.y * ar.y + v.z * ar.z + v.w * ar.w;
#pragma unroll
    for (int o = 1; o < 8; o <<= 1) {
        pl += __shfl_xor_sync(0xffffffffu, pl, o);
        pr += __shfl_xor_sync(0xffffffffu, pr, o);
    }
    if ((lane & 7) == 0) {
        int h = lane >> 3;
        g_el[wid * NHEAD + h] = pl;
        g_er[wid * NHEAD + h] = pr;
    }
}

// =================================================================
// Kernel 3: histogram of dst degrees
// =================================================================
__global__ __launch_bounds__(256) void k_hist(const int* __restrict__ dst) {
    int e = blockIdx.x * blockDim.x + threadIdx.x;
    if (e < N_EDGES) atomicAdd(&g_deg[dst[e]], 1);
}

// ---------- block-wide exclusive scan helper (256 threads) ----------
__device__ __forceinline__ int block_excl_scan_256(int v) {
    int lane = threadIdx.x & 31, wid = threadIdx.x >> 5;
    int incl = v;
#pragma unroll
    for (int o = 1; o < 32; o <<= 1) {
        int n = __shfl_up_sync(0xffffffffu, incl, o);
        if (lane >= o) incl += n;
    }
    __shared__ int wsum[8];
    if (lane == 31) wsum[wid] = incl;
    __syncthreads();
    int woff = 0;
    if (wid == 0 && lane < 8) {
        int wv = wsum[lane];
        int acc = wv;
#pragma unroll
        for (int o = 1; o < 8; o <<= 1) {
            int n = __shfl_up_sync(0xffu, acc, o);
            if (lane >= o) acc += n;
        }
        wsum[lane] = acc - wv;   // exclusive warp offsets
    }
    __syncthreads();
    woff = wsum[wid];
    return incl - v + woff;
}

// =================================================================
// Kernel 4a/4b/4c: 3-phase exclusive scan -> rowptr, cursor
// =================================================================
__global__ __launch_bounds__(256) void k_scanA() {
    int idx = blockIdx.x * 256 + threadIdx.x;
    int v = (idx < N_NODES) ? g_deg[idx] : 0;
    int excl = block_excl_scan_256(v);
    if (threadIdx.x == 255) g_poff[blockIdx.x] = excl + v;
}

__global__ __launch_bounds__(256) void k_scanB() {
    int t = threadIdx.x;
    int v = (t < SCAN_B) ? g_poff[t] : 0;
    int excl = block_excl_scan_256(v);
    if (t < SCAN_B) g_poff[t] = excl;
}

__global__ __launch_bounds__(256) void k_scanC() {
    int idx = blockIdx.x * 256 + threadIdx.x;
    int v = (idx < N_NODES) ? g_deg[idx] : 0;
    int excl = block_excl_scan_256(v) + g_poff[blockIdx.x];
    if (idx < N_NODES) {
        g_rowptr[idx] = excl;
        g_cursor[idx] = excl;
        if (idx == N_NODES - 1) g_rowptr[N_NODES] = excl + v;
    }
}

// =================================================================
// Kernel 5: scatter edges into CSR order (by dst)
// =================================================================
__global__ __launch_bounds__(256) void k_scatter(const int* __restrict__ src,
                                                 const int* __restrict__ dst,
                                                 const float* __restrict__ ew) {
    int e = blockIdx.x * blockDim.x + threadIdx.x;
    if (e >= N_EDGES) return;
    int d = dst[e];
    int pos = atomicAdd(&g_cursor[d], 1);
    g_edge[pos] = make_int2(src[e], __float_as_int(ew[e]));
}

// =================================================================
// Kernel 6: aggregation. One warp per dst node; 2-edge unrolled for MLP.
// =================================================================
__global__ __launch_bounds__(256) void k_agg(float* __restrict__ out,
                                             const float* __restrict__ Wedge,
                                             const float* __restrict__ bias) {
    int d = (blockIdx.x * blockDim.x + threadIdx.x) >> 5;
    if (d >= N_NODES) return;
    int lane = threadIdx.x & 31;
    int h = lane >> 3;

    float4 We = *(const float4*)&Wedge[lane * 4];
    float4 b4 = *(const float4*)&bias[lane * 4];

    int beg = g_rowptr[d];
    int end = g_rowptr[d + 1];
    float er_h = g_er[d * NHEAD + h];

    float4 num = make_float4(0.f, 0.f, 0.f, 0.f);
    float4 den = make_float4(0.f, 0.f, 0.f, 0.f);

    for (int base = beg; base < end; base += 32) {
        int m = end - base;
        if (m > 32) m = 32;
        int2 sw = make_int2(0, 0);
        if (lane < m) sw = g_edge[base + lane];

        int j = 0;
        for (; j + 2 <= m; j += 2) {
            int   s0 = __shfl_sync(0xffffffffu, sw.x, j);
            int   s1 = __shfl_sync(0xffffffffu, sw.x, j + 1);
            float w0 = __int_as_float(__shfl_sync(0xffffffffu, sw.y, j));
            float w1 = __int_as_float(__shfl_sync(0xffffffffu, sw.y, j + 1));
            // issue all loads up front (MLP)
            float4 ft0 = *(const float4*)&g_feat_hf[(size_t)s0 * HFD + lane * 4];
            float4 ft1 = *(const float4*)&g_feat_hf[(size_t)s1 * HFD + lane * 4];
            float el0 = __ldg(&g_el[s0 * NHEAD + h]);
            float el1 = __ldg(&g_el[s1 * NHEAD + h]);

            float c0 = el0 + er_h;
            float v0 = c0 + w0 * We.x;  v0 = fmaxf(v0, 0.2f * v0);
            float v1 = c0 + w0 * We.y;  v1 = fmaxf(v1, 0.2f * v1);
            float v2 = c0 + w0 * We.z;  v2 = fmaxf(v2, 0.2f * v2);
            float v3 = c0 + w0 * We.w;  v3 = fmaxf(v3, 0.2f * v3);
            float e0 = __expf(v0), e1 = __expf(v1), e2 = __expf(v2), e3 = __expf(v3);
            den.x += e0; den.y += e1; den.z += e2; den.w += e3;
            num.x = fmaf(e0, ft0.x, num.x);
            num.y = fmaf(e1, ft0.y, num.y);
            num.z = fmaf(e2, ft0.z, num.z);
            num.w = fmaf(e3, ft0.w, num.w);

            float c1 = el1 + er_h;
            float u0 = c1 + w1 * We.x;  u0 = fmaxf(u0, 0.2f * u0);
            float u1 = c1 + w1 * We.y;  u1 = fmaxf(u1, 0.2f * u1);
            float u2 = c1 + w1 * We.z;  u2 = fmaxf(u2, 0.2f * u2);
            float u3 = c1 + w1 * We.w;  u3 = fmaxf(u3, 0.2f * u3);
            float f0 = __expf(u0), f1 = __expf(u1), f2 = __expf(u2), f3 = __expf(u3);
            den.x += f0; den.y += f1; den.z += f2; den.w += f3;
            num.x = fmaf(f0, ft1.x, num.x);
            num.y = fmaf(f1, ft1.y, num.y);
            num.z = fmaf(f2, ft1.z, num.z);
            num.w = fmaf(f3, ft1.w, num.w);
        }
        if (j < m) {
            int   s = __shfl_sync(0xffffffffu, sw.x, j);
            float w = __int_as_float(__shfl_sync(0xffffffffu, sw.y, j));
            float4 ft = *(const float4*)&g_feat_hf[(size_t)s * HFD + lane * 4];
            float c = __ldg(&g_el[s * NHEAD + h]) + er_h;
            float v0 = c + w * We.x;  v0 = fmaxf(v0, 0.2f * v0);
            float v1 = c + w * We.y;  v1 = fmaxf(v1, 0.2f * v1);
            float v2 = c + w * We.z;  v2 = fmaxf(v2, 0.2f * v2);
            float v3 = c + w * We.w;  v3 = fmaxf(v3, 0.2f * v3);
            float e0 = __expf(v0), e1 = __expf(v1), e2 = __expf(v2), e3 = __expf(v3);
            den.x += e0; den.y += e1; den.z += e2; den.w += e3;
            num.x = fmaf(e0, ft.x, num.x);
            num.y = fmaf(e1, ft.y, num.y);
            num.z = fmaf(e2, ft.z, num.z);
            num.w = fmaf(e3, ft.w, num.w);
        }
    }

    float4 o;
    if (end > beg) {
        o.x = num.x / den.x + b4.x;
        o.y = num.y / den.y + b4.y;
        o.z = num.z / den.z + b4.z;
        o.w = num.w / den.w + b4.w;
    } else {
        o = b4;   // isolated node: just bias
    }
    *(float4*)&out[(size_t)d * HFD + lane * 4] = o;
}

// =================================================================
extern "C" void kernel_launch(void* const* d_in, const int* in_sizes, int n_in,
                              void* d_out, int out_size) {
    const float* feat   = (const float*)d_in[0];
    const float* ew     = (const float*)d_in[1];
    const int*   src    = (const int*)d_in[2];
    const int*   dst    = (const int*)d_in[3];
    const float* Wfc    = (const float*)d_in[4];
    const float* Wedge  = (const float*)d_in[5];
    const float* attn_l = (const float*)d_in[6];
    const float* attn_r = (const float*)d_in[7];
    const float* bias   = (const float*)d_in[8];
    float* out = (float*)d_out;

    (void)in_sizes; (void)n_in; (void)out_size;

    k_gemm<<<(N_NODES + 127) / 128, 256>>>(feat, Wfc);            // + deg zero
    k_elr<<<(N_NODES * 32 + 255) / 256, 256>>>(attn_l, attn_r);
    k_hist<<<(N_EDGES + 255) / 256, 256>>>(dst);
    k_scanA<<<SCAN_B, 256>>>();
    k_scanB<<<1, 256>>>();
    k_scanC<<<SCAN_B, 256>>>();
    k_scatter<<<(N_EDGES + 255) / 256, 256>>>(src, dst, ew);
    k_agg<<<(N_NODES * 32 + 255) / 256, 256>>>(out, Wedge, bias);
}

// round 5
// speedup vs baseline: 1.7051x; 1.0531x over previous
#include <cuda_runtime.h>
#include <cuda_bf16.h>

#define N_NODES 50000
#define N_EDGES 800000
#define IN_F 256
#define HFD 128   // HEADS * OUT_FEATS
#define NHEAD 4
#define SCAN_B 196   // ceil(50000/256)
#define GEMM_B 391   // ceil(50000/128)
#define HIST_B 391
#define FUSED_B (GEMM_B + HIST_B)

// -------- scratch (device globals; no allocation allowed) --------
__device__ float g_feat_hf[N_NODES * HFD];   // projected features [N,128]
__device__ float g_el[N_NODES * NHEAD];      // attn_l dot  [N,4]
__device__ float g_er[N_NODES * NHEAD];      // attn_r dot  [N,4]
__device__ int   g_deg[N_NODES];             // per-dst degree (zero-init .bss; re-zeroed by scanC)
__device__ int   g_rowptr[N_NODES + 1];      // CSR row pointers
__device__ int   g_cursor[N_NODES];          // scatter cursors
__device__ int   g_poff[SCAN_B];             // scan partials
__device__ int2  g_edge[N_EDGES];            // (src, bits(weight)) sorted by dst

__device__ __forceinline__ unsigned f2tf32(float f) {
    unsigned u;
    asm("cvt.rna.tf32.f32 %0, %1;" : "=r"(u) : "f"(f));
    return u;
}

// =================================================================
// Kernel 1 (fused): blocks [0,GEMM_B): tf32 GEMM feat @ W_fc^T with
//   el/er computed in the epilogue from accumulators.
// blocks [GEMM_B, FUSED_B): dst-degree histogram (runs concurrently).
// =================================================================
__global__ __launch_bounds__(256) void k_gemm_hist(const float* __restrict__ feat,
                                                   const float* __restrict__ Wfc,
                                                   const float* __restrict__ attn_l,
                                                   const float* __restrict__ attn_r,
                                                   const int* __restrict__ dst) {
    const int tid = threadIdx.x;

    if (blockIdx.x >= GEMM_B) {
        // ---------------- histogram part ----------------
        int b = blockIdx.x - GEMM_B;
        for (int e = b * 256 + tid; e < N_EDGES; e += HIST_B * 256)
            atomicAdd(&g_deg[__ldg(&dst[e])], 1);
        return;
    }

    // ---------------- GEMM part ----------------
    __shared__ unsigned As[32][132];   // [k][m], tf32 bits, padded
    __shared__ unsigned Bs[32][132];   // [k][n], tf32 bits, padded

    const int lane = tid & 31;
    const int wid = tid >> 5;
    const int warp_m = wid >> 2;       // 0..1
    const int warp_n = wid & 3;        // 0..3  (== head index h)
    const int row0 = blockIdx.x * 128;

    float acc[4][4][4];                // [mtile][ntile][frag]
#pragma unroll
    for (int i = 0; i < 4; i++)
#pragma unroll
        for (int j = 0; j < 4; j++)
#pragma unroll
            for (int q = 0; q < 4; q++) acc[i][j][q] = 0.f;

    const int gq = lane >> 2;          // group id 0..7 (row within 8)
    const int tg = lane & 3;           // thread-in-group 0..3 (col pair)

    for (int chunk = 0; chunk < 8; chunk++) {
        const int kglob = chunk * 32;
#pragma unroll
        for (int i = 0; i < 4; i++) {
            int idx = tid + i * 256;
            int m = idx & 127;
            int k4 = (idx >> 7) * 4;
            int row = row0 + m;
            if (row >= N_NODES) row = N_NODES - 1;
            float4 v = *(const float4*)(feat + (size_t)row * IN_F + kglob + k4);
            As[k4 + 0][m] = f2tf32(v.x);
            As[k4 + 1][m] = f2tf32(v.y);
            As[k4 + 2][m] = f2tf32(v.z);
            As[k4 + 3][m] = f2tf32(v.w);
        }
#pragma unroll
        for (int i = 0; i < 4; i++) {
            int idx = tid + i * 256;
            int n = idx & 127;
            int k4 = (idx >> 7) * 4;
            float4 v = *(const float4*)(Wfc + (size_t)n * IN_F + kglob + k4);
            Bs[k4 + 0][n] = f2tf32(v.x);
            Bs[k4 + 1][n] = f2tf32(v.y);
            Bs[k4 + 2][n] = f2tf32(v.z);
            Bs[k4 + 3][n] = f2tf32(v.w);
        }
        __syncthreads();

#pragma unroll
        for (int kk = 0; kk < 4; kk++) {
            const int kb = kk * 8;
            unsigned a[4][4], b[4][2];
#pragma unroll
            for (int mt = 0; mt < 4; mt++) {
                int rs = warp_m * 64 + mt * 16;
                a[mt][0] = As[kb + tg][rs + gq];
                a[mt][1] = As[kb + tg][rs + gq + 8];
                a[mt][2] = As[kb + tg + 4][rs + gq];
                a[mt][3] = As[kb + tg + 4][rs + gq + 8];
            }
#pragma unroll
            for (int nt = 0; nt < 4; nt++) {
                int ns = warp_n * 32 + nt * 8;
                b[nt][0] = Bs[kb + tg][ns + gq];
                b[nt][1] = Bs[kb + tg + 4][ns + gq];
            }
#pragma unroll
            for (int mt = 0; mt < 4; mt++)
#pragma unroll
                for (int nt = 0; nt < 4; nt++) {
                    asm volatile(
                        "mma.sync.aligned.m16n8k8.row.col.f32.tf32.tf32.f32 "
                        "{%0,%1,%2,%3}, {%4,%5,%6,%7}, {%8,%9}, {%0,%1,%2,%3};"
                        : "+f"(acc[mt][nt][0]), "+f"(acc[mt][nt][1]),
                          "+f"(acc[mt][nt][2]), "+f"(acc[mt][nt][3])
                        : "r"(a[mt][0]), "r"(a[mt][1]), "r"(a[mt][2]), "r"(a[mt][3]),
                          "r"(b[nt][0]), "r"(b[nt][1]));
                }
        }
        __syncthreads();
    }

    // attn vectors for this warp's 8 columns (head = warp_n)
    float al_v[8], ar_v[8];
#pragma unroll
    for (int nt = 0; nt < 4; nt++) {
        int col = warp_n * 32 + nt * 8 + tg * 2;
        al_v[nt * 2 + 0] = __ldg(&attn_l[col]);
        al_v[nt * 2 + 1] = __ldg(&attn_l[col + 1]);
        ar_v[nt * 2 + 0] = __ldg(&attn_r[col]);
        ar_v[nt * 2 + 1] = __ldg(&attn_r[col + 1]);
    }

    // epilogue: store feat_hf + compute el/er from accumulators
#pragma unroll
    for (int mt = 0; mt < 4; mt++) {
        float pl0 = 0.f, pl1 = 0.f, pr0 = 0.f, pr1 = 0.f;
#pragma unroll
        for (int nt = 0; nt < 4; nt++) {
            int col = warp_n * 32 + nt * 8 + tg * 2;
            int r0 = row0 + warp_m * 64 + mt * 16 + gq;
            if (r0 < N_NODES) {
                float2 v = make_float2(acc[mt][nt][0], acc[mt][nt][1]);
                *(float2*)&g_feat_hf[(size_t)r0 * HFD + col] = v;
            }
            int r1 = r0 + 8;
            if (r1 < N_NODES) {
                float2 v = make_float2(acc[mt][nt][2], acc[mt][nt][3]);
                *(float2*)&g_feat_hf[(size_t)r1 * HFD + col] = v;
            }
            pl0 += acc[mt][nt][0] * al_v[nt * 2] + acc[mt][nt][1] * al_v[nt * 2 + 1];
            pl1 += acc[mt][nt][2] * al_v[nt * 2] + acc[mt][nt][3] * al_v[nt * 2 + 1];
            pr0 += acc[mt][nt][0] * ar_v[nt * 2] + acc[mt][nt][1] * ar_v[nt * 2 + 1];
            pr1 += acc[mt][nt][2] * ar_v[nt * 2] + acc[mt][nt][3] * ar_v[nt * 2 + 1];
        }
        // reduce over the 4 tg lanes (lane bits 0-1)
#pragma unroll
        for (int o = 1; o < 4; o <<= 1) {
            pl0 += __shfl_xor_sync(0xffffffffu, pl0, o);
            pl1 += __shfl_xor_sync(0xffffffffu, pl1, o);
            pr0 += __shfl_xor_sync(0xffffffffu, pr0, o);
            pr1 += __shfl_xor_sync(0xffffffffu, pr1, o);
        }
        if (tg == 0) {
            int r0 = row0 + warp_m * 64 + mt * 16 + gq;
            if (r0 < N_NODES) {
                g_el[r0 * NHEAD + warp_n] = pl0;
                g_er[r0 * NHEAD + warp_n] = pr0;
            }
            int r1 = r0 + 8;
            if (r1 < N_NODES) {
                g_el[r1 * NHEAD + warp_n] = pl1;
                g_er[r1 * NHEAD + warp_n] = pr1;
            }
        }
    }
}

// ---------- block-wide exclusive scan helper (256 threads) ----------
__device__ __forceinline__ int block_excl_scan_256(int v) {
    int lane = threadIdx.x & 31, wid = threadIdx.x >> 5;
    int incl = v;
#pragma unroll
    for (int o = 1; o < 32; o <<= 1) {
        int n = __shfl_up_sync(0xffffffffu, incl, o);
        if (lane >= o) incl += n;
    }
    __shared__ int wsum[8];
    if (lane == 31) wsum[wid] = incl;
    __syncthreads();
    int woff = 0;
    if (wid == 0 && lane < 8) {
        int wv = wsum[lane];
        int acc = wv;
#pragma unroll
        for (int o = 1; o < 8; o <<= 1) {
            int n = __shfl_up_sync(0xffu, acc, o);
            if (lane >= o) acc += n;
        }
        wsum[lane] = acc - wv;   // exclusive warp offsets
    }
    __syncthreads();
    woff = wsum[wid];
    return incl - v + woff;
}

// =================================================================
// 3-phase exclusive scan -> rowptr, cursor.  scanC re-zeroes g_deg
// so the next graph replay's histogram starts from zero.
// =================================================================
__global__ __launch_bounds__(256) void k_scanA() {
    int idx = blockIdx.x * 256 + threadIdx.x;
    int v = (idx < N_NODES) ? g_deg[idx] : 0;
    int excl = block_excl_scan_256(v);
    if (threadIdx.x == 255) g_poff[blockIdx.x] = excl + v;
}

__global__ __launch_bounds__(256) void k_scanB() {
    int t = threadIdx.x;
    int v = (t < SCAN_B) ? g_poff[t] : 0;
    int excl = block_excl_scan_256(v);
    if (t < SCAN_B) g_poff[t] = excl;
}

__global__ __launch_bounds__(256) void k_scanC() {
    int idx = blockIdx.x * 256 + threadIdx.x;
    int v = (idx < N_NODES) ? g_deg[idx] : 0;
    int excl = block_excl_scan_256(v) + g_poff[blockIdx.x];
    if (idx < N_NODES) {
        g_rowptr[idx] = excl;
        g_cursor[idx] = excl;
        g_deg[idx] = 0;                       // self-clean for next replay
        if (idx == N_NODES - 1) g_rowptr[N_NODES] = excl + v;
    }
}

// =================================================================
// scatter edges into CSR order (by dst)
// =================================================================
__global__ __launch_bounds__(256) void k_scatter(const int* __restrict__ src,
                                                 const int* __restrict__ dst,
                                                 const float* __restrict__ ew) {
    int e = blockIdx.x * blockDim.x + threadIdx.x;
    if (e >= N_EDGES) return;
    int d = dst[e];
    int pos = atomicAdd(&g_cursor[d], 1);
    g_edge[pos] = make_int2(src[e], __float_as_int(ew[e]));
}

// =================================================================
// aggregation. One warp per dst node; 2-edge unrolled for MLP.
// =================================================================
__global__ __launch_bounds__(256) void k_agg(float* __restrict__ out,
                                             const float* __restrict__ Wedge,
                                             const float* __restrict__ bias) {
    int d = (blockIdx.x * blockDim.x + threadIdx.x) >> 5;
    if (d >= N_NODES) return;
    int lane = threadIdx.x & 31;
    int h = lane >> 3;

    float4 We = *(const float4*)&Wedge[lane * 4];
    float4 b4 = *(const float4*)&bias[lane * 4];

    int beg = g_rowptr[d];
    int end = g_rowptr[d + 1];
    float er_h = g_er[d * NHEAD + h];

    float4 num = make_float4(0.f, 0.f, 0.f, 0.f);
    float4 den = make_float4(0.f, 0.f, 0.f, 0.f);

    for (int base = beg; base < end; base += 32) {
        int m = end - base;
        if (m > 32) m = 32;
        int2 sw = make_int2(0, 0);
        if (lane < m) sw = g_edge[base + lane];

        int j = 0;
        for (; j + 2 <= m; j += 2) {
            int   s0 = __shfl_sync(0xffffffffu, sw.x, j);
            int   s1 = __shfl_sync(0xffffffffu, sw.x, j + 1);
            float w0 = __int_as_float(__shfl_sync(0xffffffffu, sw.y, j));
            float w1 = __int_as_float(__shfl_sync(0xffffffffu, sw.y, j + 1));
            float4 ft0 = *(const float4*)&g_feat_hf[(size_t)s0 * HFD + lane * 4];
            float4 ft1 = *(const float4*)&g_feat_hf[(size_t)s1 * HFD + lane * 4];
            float el0 = __ldg(&g_el[s0 * NHEAD + h]);
            float el1 = __ldg(&g_el[s1 * NHEAD + h]);

            float c0 = el0 + er_h;
            float v0 = c0 + w0 * We.x;  v0 = fmaxf(v0, 0.2f * v0);
            float v1 = c0 + w0 * We.y;  v1 = fmaxf(v1, 0.2f * v1);
            float v2 = c0 + w0 * We.z;  v2 = fmaxf(v2, 0.2f * v2);
            float v3 = c0 + w0 * We.w;  v3 = fmaxf(v3, 0.2f * v3);
            float e0 = __expf(v0), e1 = __expf(v1), e2 = __expf(v2), e3 = __expf(v3);
            den.x += e0; den.y += e1; den.z += e2; den.w += e3;
            num.x = fmaf(e0, ft0.x, num.x);
            num.y = fmaf(e1, ft0.y, num.y);
            num.z = fmaf(e2, ft0.z, num.z);
            num.w = fmaf(e3, ft0.w, num.w);

            float c1 = el1 + er_h;
            float u0 = c1 + w1 * We.x;  u0 = fmaxf(u0, 0.2f * u0);
            float u1 = c1 + w1 * We.y;  u1 = fmaxf(u1, 0.2f * u1);
            float u2 = c1 + w1 * We.z;  u2 = fmaxf(u2, 0.2f * u2);
            float u3 = c1 + w1 * We.w;  u3 = fmaxf(u3, 0.2f * u3);
            float f0 = __expf(u0), f1 = __expf(u1), f2 = __expf(u2), f3 = __expf(u3);
            den.x += f0; den.y += f1; den.z += f2; den.w += f3;
            num.x = fmaf(f0, ft1.x, num.x);
            num.y = fmaf(f1, ft1.y, num.y);
            num.z = fmaf(f2, ft1.z, num.z);
            num.w = fmaf(f3, ft1.w, num.w);
        }
        if (j < m) {
            int   s = __shfl_sync(0xffffffffu, sw.x, j);
            float w = __int_as_float(__shfl_sync(0xffffffffu, sw.y, j));
            float4 ft = *(const float4*)&g_feat_hf[(size_t)s * HFD + lane * 4];
            float c = __ldg(&g_el[s * NHEAD + h]) + er_h;
            float v0 = c + w * We.x;  v0 = fmaxf(v0, 0.2f * v0);
            float v1 = c + w * We.y;  v1 = fmaxf(v1, 0.2f * v1);
            float v2 = c + w * We.z;  v2 = fmaxf(v2, 0.2f * v2);
            float v3 = c + w * We.w;  v3 = fmaxf(v3, 0.2f * v3);
            float e0 = __expf(v0), e1 = __expf(v1), e2 = __expf(v2), e3 = __expf(v3);
            den.x += e0; den.y += e1; den.z += e2; den.w += e3;
            num.x = fmaf(e0, ft.x, num.x);
            num.y = fmaf(e1, ft.y, num.y);
            num.z = fmaf(e2, ft.z, num.z);
            num.w = fmaf(e3, ft.w, num.w);
        }
    }

    float4 o;
    if (end > beg) {
        o.x = num.x / den.x + b4.x;
        o.y = num.y / den.y + b4.y;
        o.z = num.z / den.z + b4.z;
        o.w = num.w / den.w + b4.w;
    } else {
        o = b4;   // isolated node: just bias
    }
    *(float4*)&out[(size_t)d * HFD + lane * 4] = o;
}

// =================================================================
extern "C" void kernel_launch(void* const* d_in, const int* in_sizes, int n_in,
                              void* d_out, int out_size) {
    const float* feat   = (const float*)d_in[0];
    const float* ew     = (const float*)d_in[1];
    const int*   src    = (const int*)d_in[2];
    const int*   dst    = (const int*)d_in[3];
    const float* Wfc    = (const float*)d_in[4];
    const float* Wedge  = (const float*)d_in[5];
    const float* attn_l = (const float*)d_in[6];
    const float* attn_r = (const float*)d_in[7];
    const float* bias   = (const float*)d_in[8];
    float* out = (float*)d_out;

    (void)in_sizes; (void)n_in; (void)out_size;

    k_gemm_hist<<<FUSED_B, 256>>>(feat, Wfc, attn_l, attn_r, dst);
    k_scanA<<<SCAN_B, 256>>>();
    k_scanB<<<1, 256>>>();
    k_scanC<<<SCAN_B, 256>>>();
    k_scatter<<<(N_EDGES + 255) / 256, 256>>>(src, dst, ew);
    k_agg<<<(N_NODES * 32 + 255) / 256, 256>>>(out, Wedge, bias);
}